// round 2
// baseline (speedup 1.0000x reference)
#include <cuda_runtime.h>
#include <cstdint>

// Problem dims
constexpr int B_ = 8;
constexpr int H_ = 9;
constexpr int E_ = 128;
constexpr int S_ = 1025;
constexpr long long QKV_ELEMS = (long long)B_ * H_ * S_ * E_;   // 9,446,400
constexpr long long O_ELEMS   = (long long)B_ * S_ * H_ * E_;   // 9,446,400

// Scratch (device globals: allocation-free per harness rules)
__device__ float g_q[QKV_ELEMS];
__device__ float g_k[QKV_ELEMS];
__device__ float g_v[QKV_ELEMS];
__device__ float g_o[O_ELEMS];

// ---------------------------------------------------------------------------
// cp.async helpers
// ---------------------------------------------------------------------------
__device__ __forceinline__ void cp_async4(uint32_t dst, const float* src, bool p) {
    int sz = p ? 4 : 0;
    asm volatile("cp.async.ca.shared.global [%0], [%1], 4, %2;\n"
                 :: "r"(dst), "l"(src), "r"(sz));
}
__device__ __forceinline__ void cp_commit() {
    asm volatile("cp.async.commit_group;\n" ::: "memory");
}
template <int N>
__device__ __forceinline__ void cp_wait() {
    asm volatile("cp.async.wait_group %0;\n" :: "n"(N) : "memory");
}

// ---------------------------------------------------------------------------
// Register-blocked SGEMM tile: C[M,N] = scale * A[M,K]*B[K,N] (+bias[n]),
// arbitrary element strides. A_KC/B_KC: true if the operand's K-stride is 1.
// BM=BN=128, BK=16, 256 threads, 8x8 microtile as 2x2 blocks of 4x4.
// Double-buffered smem, cp.async pipeline.
// ---------------------------------------------------------------------------
template<bool A_KC, bool B_KC>
__device__ __forceinline__ void sgemm128(
    const float* __restrict__ A, long long a_m, long long a_k,
    const float* __restrict__ Bp, long long b_n, long long b_k,
    float* __restrict__ C, long long c_m, long long c_n,
    int M, int N, int K, float scale, const float* __restrict__ bias)
{
    constexpr int BM = 128, BN = 128, BK = 16;
    constexpr int LDAS = BM + 4;  // 132 floats/row; 528B = 33*16 (16B aligned rows)
    __shared__ float As[2][BK][LDAS];
    __shared__ float Bs[2][BK][LDAS];

    const int tid  = threadIdx.x;
    const int tx   = tid & 15;
    const int ty   = tid >> 4;
    const int m0   = blockIdx.x * BM;
    const int n0   = blockIdx.y * BN;

    const uint32_t as_base = (uint32_t)__cvta_generic_to_shared(&As[0][0][0]);
    const uint32_t bs_base = (uint32_t)__cvta_generic_to_shared(&Bs[0][0][0]);

    auto load_tile = [&](int kt, int stage) {
        const int k0 = kt * BK;
        // A tile: BM*BK = 2048 elems / 256 threads = 8 each
#pragma unroll
        for (int c = 0; c < (BM * BK) / 256; ++c) {
            int li = c * 256 + tid;
            int m, k;
            if (A_KC) { k = li & 15;  m = li >> 4; }
            else      { m = li & 127; k = li >> 7; }
            int gm = m0 + m, gk = k0 + k;
            bool p = (gm < M) && (gk < K);
            const float* src = p ? (A + (long long)gm * a_m + (long long)gk * a_k) : A;
            uint32_t dst = as_base + (uint32_t)(((stage * BK + k) * LDAS + m) * 4);
            cp_async4(dst, src, p);
        }
        // B tile
#pragma unroll
        for (int c = 0; c < (BN * BK) / 256; ++c) {
            int li = c * 256 + tid;
            int n, k;
            if (B_KC) { k = li & 15;  n = li >> 4; }
            else      { n = li & 127; k = li >> 7; }
            int gn = n0 + n, gk = k0 + k;
            bool p = (gn < N) && (gk < K);
            const float* src = p ? (Bp + (long long)gn * b_n + (long long)gk * b_k) : Bp;
            uint32_t dst = bs_base + (uint32_t)(((stage * BK + k) * LDAS + n) * 4);
            cp_async4(dst, src, p);
        }
    };

    float acc[8][8];
#pragma unroll
    for (int i = 0; i < 8; ++i)
#pragma unroll
        for (int j = 0; j < 8; ++j) acc[i][j] = 0.0f;

    const int ktiles = (K + BK - 1) / BK;

    load_tile(0, 0);
    cp_commit();

    int buf = 0;
    for (int kt = 0; kt < ktiles; ++kt) {
        if (kt + 1 < ktiles) load_tile(kt + 1, buf ^ 1);
        cp_commit();
        cp_wait<1>();          // everything except the newest group is done
        __syncthreads();

#pragma unroll
        for (int k = 0; k < BK; ++k) {
            float4 a0 = *reinterpret_cast<const float4*>(&As[buf][k][ty * 4]);
            float4 a1 = *reinterpret_cast<const float4*>(&As[buf][k][64 + ty * 4]);
            float4 b0 = *reinterpret_cast<const float4*>(&Bs[buf][k][tx * 4]);
            float4 b1 = *reinterpret_cast<const float4*>(&Bs[buf][k][64 + tx * 4]);
            float af[8] = {a0.x, a0.y, a0.z, a0.w, a1.x, a1.y, a1.z, a1.w};
            float bf[8] = {b0.x, b0.y, b0.z, b0.w, b1.x, b1.y, b1.z, b1.w};
#pragma unroll
            for (int i = 0; i < 8; ++i)
#pragma unroll
                for (int j = 0; j < 8; ++j)
                    acc[i][j] = fmaf(af[i], bf[j], acc[i][j]);
        }
        __syncthreads();       // protect this buf: next iteration's cp.async overwrites it
        buf ^= 1;
    }

    // ---- epilogue ----
#pragma unroll
    for (int i = 0; i < 8; ++i) {
        int lr = (i < 4) ? (ty * 4 + i) : (64 + ty * 4 + i - 4);
        int gm = m0 + lr;
        if (gm >= M) continue;
#pragma unroll
        for (int j = 0; j < 8; ++j) {
            int lc = (j < 4) ? (tx * 4 + j) : (64 + tx * 4 + j - 4);
            int gn = n0 + lc;
            if (gn >= N) continue;
            float v = acc[i][j] * scale;
            if (bias) v += bias[gn];
            C[(long long)gm * c_m + (long long)gn * c_n] = v;
        }
    }
}

// ---------------------------------------------------------------------------
// Stage 1: q/k/v[b,h,s,f] = sum_e x[b,e,s] * {Q,K,V}[h,e,f]
// blockIdx.z = p*(B*H) + bh,  p in {0,1,2}
// ---------------------------------------------------------------------------
__global__ __launch_bounds__(256, 2) void qkv_kernel(
    const float* __restrict__ x, const float* __restrict__ Qm,
    const float* __restrict__ Km, const float* __restrict__ Vm)
{
    const int z  = blockIdx.z;
    const int bh = z % (B_ * H_);
    const int p  = z / (B_ * H_);
    const int b  = bh / H_;
    const int h  = bh % H_;
    const float* A  = x + (long long)b * E_ * S_;           // (m=s,k=e): x[k*S + m]
    const float* Bp = (p == 0 ? Qm : (p == 1 ? Km : Vm)) + (long long)h * E_ * E_;
    float* C = (p == 0 ? g_q : (p == 1 ? g_k : g_v)) + (long long)bh * S_ * E_;
    sgemm128<false, false>(A, /*a_m=*/1, /*a_k=*/S_,
                           Bp, /*b_n=*/1, /*b_k=*/E_,
                           C,  /*c_m=*/E_, /*c_n=*/1,
                           S_, E_, E_, 1.0f, nullptr);
}

// ---------------------------------------------------------------------------
// Stage 2: raw scores into atten region: cor[s,t] = (q[s]·k[t]) / sqrt(E)
// ---------------------------------------------------------------------------
__global__ __launch_bounds__(256, 2) void scores_kernel(float* __restrict__ att)
{
    const int bh = blockIdx.z;
    const float* A  = g_q + (long long)bh * S_ * E_;
    const float* Bp = g_k + (long long)bh * S_ * E_;
    float* C = att + (long long)bh * S_ * S_;
    sgemm128<true, true>(A, E_, 1,
                         Bp, E_, 1,
                         C, S_, 1,
                         S_, S_, E_, 0.08838834764831845f, nullptr);
}

// ---------------------------------------------------------------------------
// Stage 3: in-place row softmax over length S=1025. One 256-thread block/row.
// ---------------------------------------------------------------------------
__global__ __launch_bounds__(256) void softmax_kernel(float* __restrict__ att)
{
    const long long row = blockIdx.x;
    float* p = att + row * (long long)S_;
    const int tid = threadIdx.x;

    float v[5];
    float mx = -3.4e38f;
#pragma unroll
    for (int i = 0; i < 5; ++i) {
        int idx = tid + i * 256;
        v[i] = (idx < S_) ? p[idx] : -3.4e38f;
        mx = fmaxf(mx, v[i]);
    }
    __shared__ float redm[8];
    __shared__ float reds[8];
#pragma unroll
    for (int o = 16; o > 0; o >>= 1) mx = fmaxf(mx, __shfl_xor_sync(0xffffffffu, mx, o));
    if ((tid & 31) == 0) redm[tid >> 5] = mx;
    __syncthreads();
    mx = redm[0];
#pragma unroll
    for (int w = 1; w < 8; ++w) mx = fmaxf(mx, redm[w]);

    float sum = 0.0f;
#pragma unroll
    for (int i = 0; i < 5; ++i) {
        int idx = tid + i * 256;
        if (idx < S_) { v[i] = __expf(v[i] - mx); sum += v[i]; }
        else v[i] = 0.0f;
    }
#pragma unroll
    for (int o = 16; o > 0; o >>= 1) sum += __shfl_xor_sync(0xffffffffu, sum, o);
    if ((tid & 31) == 0) reds[tid >> 5] = sum;
    __syncthreads();
    sum = reds[0];
#pragma unroll
    for (int w = 1; w < 8; ++w) sum += reds[w];
    const float inv = __frcp_rn(sum);

#pragma unroll
    for (int i = 0; i < 5; ++i) {
        int idx = tid + i * 256;
        if (idx < S_) p[idx] = v[i] * inv;
    }
}

// ---------------------------------------------------------------------------
// Stage 4: o[b,s,h*E+f] = sum_t atten[b,h,s,t] * v[b,h,t,f]
// (written in [B,S,H*E] layout so the final projection is a clean GEMM)
// ---------------------------------------------------------------------------
__global__ __launch_bounds__(256, 2) void av_kernel(const float* __restrict__ att)
{
    const int bh = blockIdx.z;
    const int b = bh / H_;
    const int h = bh % H_;
    const float* A  = att + (long long)bh * S_ * S_;
    const float* Bp = g_v + (long long)bh * S_ * E_;
    float* C = g_o + (long long)b * S_ * (H_ * E_) + (long long)h * E_;
    sgemm128<true, false>(A, S_, 1,
                          Bp, 1, E_,
                          C, (long long)(H_ * E_), 1,
                          S_, E_, S_, 1.0f, nullptr);
}

// ---------------------------------------------------------------------------
// Stage 5: out[b,e,s] = sum_k o[b,s,k] * W[e,k] + bias[e]   (K = H*E = 1152)
// C stored transposed: c_m(s)=1, c_n(e)=S
// ---------------------------------------------------------------------------
__global__ __launch_bounds__(256, 2) void proj_kernel(
    const float* __restrict__ W, const float* __restrict__ bias,
    float* __restrict__ out)
{
    const int b = blockIdx.z;
    const float* A = g_o + (long long)b * S_ * (H_ * E_);
    float* C = out + (long long)b * E_ * S_;
    sgemm128<true, true>(A, (long long)(H_ * E_), 1,
                         W, (long long)(H_ * E_), 1,
                         C, 1, S_,
                         S_, E_, H_ * E_, 1.0f, bias);
}

// ---------------------------------------------------------------------------
extern "C" void kernel_launch(void* const* d_in, const int* in_sizes, int n_in,
                              void* d_out, int out_size)
{
    (void)in_sizes; (void)n_in; (void)out_size;
    const float* x    = (const float*)d_in[0];
    const float* Qm   = (const float*)d_in[1];
    const float* Km   = (const float*)d_in[2];
    const float* Vm   = (const float*)d_in[3];
    const float* W    = (const float*)d_in[4];
    const float* bias = (const float*)d_in[5];

    float* out = (float*)d_out;
    float* att = out + (long long)B_ * E_ * S_;   // atten region follows out

    const int MT = (S_ + 127) / 128;  // 9

    qkv_kernel    <<<dim3(MT, 1, B_ * H_ * 3), 256>>>(x, Qm, Km, Vm);
    scores_kernel <<<dim3(MT, MT, B_ * H_),    256>>>(att);
    softmax_kernel<<<dim3(B_ * H_ * S_),       256>>>(att);
    av_kernel     <<<dim3(MT, 1, B_ * H_),     256>>>(att);
    proj_kernel   <<<dim3(MT, 1, B_),          256>>>(W, bias, out);
}

// round 4
// speedup vs baseline: 1.4126x; 1.4126x over previous
#include <cuda_runtime.h>
#include <cstdint>

// Problem dims
constexpr int B_ = 8;
constexpr int H_ = 9;
constexpr int E_ = 128;
constexpr int S_ = 1025;
constexpr long long QKV_ELEMS = (long long)B_ * H_ * S_ * E_;   // 9,446,400
constexpr long long O_ELEMS   = (long long)B_ * S_ * H_ * E_;   // 9,446,400

// Scratch (device globals: allocation-free per harness rules)
__device__ float g_q[QKV_ELEMS];
__device__ float g_k[QKV_ELEMS];
__device__ float g_v[QKV_ELEMS];
__device__ float g_o[O_ELEMS];

// ---------------------------------------------------------------------------
// cp.async helpers
// ---------------------------------------------------------------------------
__device__ __forceinline__ void cp_async4(uint32_t dst, const float* src, bool p) {
    int sz = p ? 4 : 0;
    asm volatile("cp.async.ca.shared.global [%0], [%1], 4, %2;\n"
                 :: "r"(dst), "l"(src), "r"(sz));
}
__device__ __forceinline__ void cp_commit() {
    asm volatile("cp.async.commit_group;\n" ::: "memory");
}
template <int N>
__device__ __forceinline__ void cp_wait() {
    asm volatile("cp.async.wait_group %0;\n" :: "n"(N) : "memory");
}

// ---------------------------------------------------------------------------
// tf32 helpers
// ---------------------------------------------------------------------------
__device__ __forceinline__ uint32_t f2tf32(float x) {
    uint32_t r;
    asm("cvt.rna.tf32.f32 %0, %1;" : "=r"(r) : "f"(x));
    return r;
}
__device__ __forceinline__ void mma8(float* c,
    uint32_t a0, uint32_t a1, uint32_t a2, uint32_t a3,
    uint32_t b0, uint32_t b1)
{
    asm volatile(
        "mma.sync.aligned.m16n8k8.row.col.f32.tf32.tf32.f32 "
        "{%0,%1,%2,%3},{%4,%5,%6,%7},{%8,%9},{%0,%1,%2,%3};"
        : "+f"(c[0]), "+f"(c[1]), "+f"(c[2]), "+f"(c[3])
        : "r"(a0), "r"(a1), "r"(a2), "r"(a3), "r"(b0), "r"(b1));
}

// ---------------------------------------------------------------------------
// Tensor-core GEMM tile: C[M,N] = scale * A[M,K]*B[K,N] (+bias[n]).
// Arbitrary element strides; X_KC true iff that operand's K-stride is 1.
// BM=BN=128, BK=16, 256 threads = 8 warps (4m x 2n), warp tile 32x64.
// mma.sync m16n8k8 tf32; SPLIT enables 3xTF32 for ~fp32 accuracy.
// Smem layouts: KC operand -> [m][k] ld=20; non-KC -> [k][m] ld=136.
// Both are bank-conflict-free for the m16n8k8 fragment read pattern.
// ---------------------------------------------------------------------------
template<bool A_KC, bool B_KC, bool SPLIT>
__device__ __forceinline__ void mma_gemm(
    const float* __restrict__ A, long long a_m, long long a_k,
    const float* __restrict__ Bp, long long b_n, long long b_k,
    float* __restrict__ C, long long c_m, long long c_n,
    int M, int N, int K, float scale, const float* __restrict__ bias)
{
    constexpr int BM = 128, BN = 128, BK = 16;
    constexpr int LDK = 20;    // [outer][k] row stride (k-contiguous operands)
    constexpr int LDX = 136;   // [k][outer] row stride
    constexpr int ASZ = A_KC ? BM * LDK : BK * LDX;
    constexpr int BSZ = B_KC ? BN * LDK : BK * LDX;
    __shared__ float sA[2 * ASZ];
    __shared__ float sB[2 * BSZ];

    const int tid  = threadIdx.x;
    const int lane = tid & 31;
    const int wid  = tid >> 5;
    const int g    = lane >> 2;   // 0..7
    const int tg   = lane & 3;    // 0..3
    const int wm   = (wid & 3) * 32;
    const int wn   = (wid >> 2) * 64;
    const int m0   = blockIdx.x * BM;
    const int n0   = blockIdx.y * BN;

    const uint32_t sa_base = (uint32_t)__cvta_generic_to_shared(sA);
    const uint32_t sb_base = (uint32_t)__cvta_generic_to_shared(sB);

    auto aOff = [](int s, int k, int m) {
        return A_KC ? (s * ASZ + m * LDK + k) : (s * ASZ + k * LDX + m);
    };
    auto bOff = [](int s, int k, int n) {
        return B_KC ? (s * BSZ + n * LDK + k) : (s * BSZ + k * LDX + n);
    };

    auto load_tile = [&](int kt, int stage) {
        const int k0 = kt * BK;
#pragma unroll
        for (int c = 0; c < (BM * BK) / 256; ++c) {
            int li = c * 256 + tid;
            int m, k;
            if (A_KC) { k = li & 15;  m = li >> 4; }
            else      { m = li & 127; k = li >> 7; }
            int gm = m0 + m, gk = k0 + k;
            bool p = (gm < M) && (gk < K);
            const float* src = p ? (A + (long long)gm * a_m + (long long)gk * a_k) : A;
            cp_async4(sa_base + (uint32_t)(aOff(stage, k, m) * 4), src, p);
        }
#pragma unroll
        for (int c = 0; c < (BN * BK) / 256; ++c) {
            int li = c * 256 + tid;
            int n, k;
            if (B_KC) { k = li & 15;  n = li >> 4; }
            else      { n = li & 127; k = li >> 7; }
            int gn = n0 + n, gk = k0 + k;
            bool p = (gn < N) && (gk < K);
            const float* src = p ? (Bp + (long long)gn * b_n + (long long)gk * b_k) : Bp;
            cp_async4(sb_base + (uint32_t)(bOff(stage, k, n) * 4), src, p);
        }
    };

    float acc[2][8][4];
#pragma unroll
    for (int i = 0; i < 2; ++i)
#pragma unroll
        for (int j = 0; j < 8; ++j)
#pragma unroll
            for (int r = 0; r < 4; ++r) acc[i][j][r] = 0.0f;

    const int ktiles = (K + BK - 1) / BK;

    load_tile(0, 0);
    cp_commit();

    int buf = 0;
    for (int kt = 0; kt < ktiles; ++kt) {
        if (kt + 1 < ktiles) load_tile(kt + 1, buf ^ 1);
        cp_commit();
        cp_wait<1>();
        __syncthreads();

#pragma unroll
        for (int ks = 0; ks < 2; ++ks) {
            const int kk = ks * 8;
            // ---- A fragments (2 m-tiles) ----
            uint32_t Ah[2][4], Al[2][4];
#pragma unroll
            for (int mf = 0; mf < 2; ++mf) {
                const int rm = wm + mf * 16;
                float f0 = sA[aOff(buf, kk + tg,     rm + g)];
                float f1 = sA[aOff(buf, kk + tg,     rm + 8 + g)];
                float f2 = sA[aOff(buf, kk + tg + 4, rm + g)];
                float f3 = sA[aOff(buf, kk + tg + 4, rm + 8 + g)];
                Ah[mf][0] = f2tf32(f0); Ah[mf][1] = f2tf32(f1);
                Ah[mf][2] = f2tf32(f2); Ah[mf][3] = f2tf32(f3);
                if (SPLIT) {
                    Al[mf][0] = f2tf32(f0 - __uint_as_float(Ah[mf][0]));
                    Al[mf][1] = f2tf32(f1 - __uint_as_float(Ah[mf][1]));
                    Al[mf][2] = f2tf32(f2 - __uint_as_float(Ah[mf][2]));
                    Al[mf][3] = f2tf32(f3 - __uint_as_float(Ah[mf][3]));
                }
            }
            // ---- B fragments in halves of 4 n-tiles (register pressure) ----
#pragma unroll
            for (int nh = 0; nh < 2; ++nh) {
                uint32_t Bh[4][2], Bl[4][2];
#pragma unroll
                for (int j = 0; j < 4; ++j) {
                    const int nb = wn + (nh * 4 + j) * 8;
                    float q0 = sB[bOff(buf, kk + tg,     nb + g)];
                    float q1 = sB[bOff(buf, kk + tg + 4, nb + g)];
                    Bh[j][0] = f2tf32(q0); Bh[j][1] = f2tf32(q1);
                    if (SPLIT) {
                        Bl[j][0] = f2tf32(q0 - __uint_as_float(Bh[j][0]));
                        Bl[j][1] = f2tf32(q1 - __uint_as_float(Bh[j][1]));
                    }
                }
#pragma unroll
                for (int mf = 0; mf < 2; ++mf)
#pragma unroll
                    for (int j = 0; j < 4; ++j) {
                        float* c = acc[mf][nh * 4 + j];
                        if (SPLIT) {
                            mma8(c, Ah[mf][0], Ah[mf][1], Ah[mf][2], Ah[mf][3],
                                 Bl[j][0], Bl[j][1]);
                            mma8(c, Al[mf][0], Al[mf][1], Al[mf][2], Al[mf][3],
                                 Bh[j][0], Bh[j][1]);
                        }
                        mma8(c, Ah[mf][0], Ah[mf][1], Ah[mf][2], Ah[mf][3],
                             Bh[j][0], Bh[j][1]);
                    }
            }
        }
        __syncthreads();
        buf ^= 1;
    }

    // ---- epilogue ----
#pragma unroll
    for (int mf = 0; mf < 2; ++mf) {
#pragma unroll
        for (int nf = 0; nf < 8; ++nf) {
            const int r0 = m0 + wm + mf * 16 + g;
            const int r1 = r0 + 8;
            const int cb = n0 + wn + nf * 8 + 2 * tg;
            float v0 = acc[mf][nf][0] * scale;
            float v1 = acc[mf][nf][1] * scale;
            float v2 = acc[mf][nf][2] * scale;
            float v3 = acc[mf][nf][3] * scale;
            if (bias) {
                if (cb < N)     { v0 += bias[cb];     v2 += bias[cb]; }
                if (cb + 1 < N) { v1 += bias[cb + 1]; v3 += bias[cb + 1]; }
            }
            if (r0 < M) {
                if (cb < N)     C[(long long)r0 * c_m + (long long)cb * c_n] = v0;
                if (cb + 1 < N) C[(long long)r0 * c_m + (long long)(cb + 1) * c_n] = v1;
            }
            if (r1 < M) {
                if (cb < N)     C[(long long)r1 * c_m + (long long)cb * c_n] = v2;
                if (cb + 1 < N) C[(long long)r1 * c_m + (long long)(cb + 1) * c_n] = v3;
            }
        }
    }
}

// ---------------------------------------------------------------------------
// Stage 1: q/k/v[b,h,s,f] = sum_e x[b,e,s] * {Q,K,V}[h,e,f]   (3xTF32)
// ---------------------------------------------------------------------------
__global__ __launch_bounds__(256, 2) void qkv_kernel(
    const float* __restrict__ x, const float* __restrict__ Qm,
    const float* __restrict__ Km, const float* __restrict__ Vm)
{
    const int z  = blockIdx.z;
    const int bh = z % (B_ * H_);
    const int p  = z / (B_ * H_);
    const int b  = bh / H_;
    const int h  = bh % H_;
    const float* A  = x + (long long)b * E_ * S_;           // A[m=s][k=e]: +k*S+m
    const float* Bp = (p == 0 ? Qm : (p == 1 ? Km : Vm)) + (long long)h * E_ * E_;
    float* C = (p == 0 ? g_q : (p == 1 ? g_k : g_v)) + (long long)bh * S_ * E_;
    mma_gemm<false, false, true>(A, 1, S_,
                                 Bp, 1, E_,
                                 C, E_, 1,
                                 S_, E_, E_, 1.0f, nullptr);
}

// ---------------------------------------------------------------------------
// Stage 2: raw scores into atten region: cor[s,t] = (q[s]·k[t]) / sqrt(E)  (3xTF32)
// ---------------------------------------------------------------------------
__global__ __launch_bounds__(256, 2) void scores_kernel(float* __restrict__ att)
{
    const int bh = blockIdx.z;
    const float* A  = g_q + (long long)bh * S_ * E_;
    const float* Bp = g_k + (long long)bh * S_ * E_;
    float* C = att + (long long)bh * S_ * S_;
    mma_gemm<true, true, true>(A, E_, 1,
                               Bp, E_, 1,
                               C, S_, 1,
                               S_, S_, E_, 0.08838834764831845f, nullptr);
}

// ---------------------------------------------------------------------------
// Stage 3: in-place row softmax over length S=1025. One 256-thread block/row.
// ---------------------------------------------------------------------------
__global__ __launch_bounds__(256) void softmax_kernel(float* __restrict__ att)
{
    const long long row = blockIdx.x;
    float* p = att + row * (long long)S_;
    const int tid = threadIdx.x;

    float v[5];
    float mx = -3.4e38f;
#pragma unroll
    for (int i = 0; i < 5; ++i) {
        int idx = tid + i * 256;
        v[i] = (idx < S_) ? p[idx] : -3.4e38f;
        mx = fmaxf(mx, v[i]);
    }
    __shared__ float redm[8];
    __shared__ float reds[8];
#pragma unroll
    for (int o = 16; o > 0; o >>= 1) mx = fmaxf(mx, __shfl_xor_sync(0xffffffffu, mx, o));
    if ((tid & 31) == 0) redm[tid >> 5] = mx;
    __syncthreads();
    mx = redm[0];
#pragma unroll
    for (int w = 1; w < 8; ++w) mx = fmaxf(mx, redm[w]);

    float sum = 0.0f;
#pragma unroll
    for (int i = 0; i < 5; ++i) {
        int idx = tid + i * 256;
        if (idx < S_) { v[i] = __expf(v[i] - mx); sum += v[i]; }
        else v[i] = 0.0f;
    }
#pragma unroll
    for (int o = 16; o > 0; o >>= 1) sum += __shfl_xor_sync(0xffffffffu, sum, o);
    if ((tid & 31) == 0) reds[tid >> 5] = sum;
    __syncthreads();
    sum = reds[0];
#pragma unroll
    for (int w = 1; w < 8; ++w) sum += reds[w];
    const float inv = __frcp_rn(sum);

#pragma unroll
    for (int i = 0; i < 5; ++i) {
        int idx = tid + i * 256;
        if (idx < S_) p[idx] = v[i] * inv;
    }
}

// ---------------------------------------------------------------------------
// Stage 4: o[b,s,h*E+f] = sum_t atten[b,h,s,t] * v[b,h,t,f]   (single tf32)
// ---------------------------------------------------------------------------
__global__ __launch_bounds__(256, 2) void av_kernel(const float* __restrict__ att)
{
    const int bh = blockIdx.z;
    const int b = bh / H_;
    const int h = bh % H_;
    const float* A  = att + (long long)bh * S_ * S_;
    const float* Bp = g_v + (long long)bh * S_ * E_;
    float* C = g_o + (long long)b * S_ * (H_ * E_) + (long long)h * E_;
    mma_gemm<true, false, false>(A, S_, 1,
                                 Bp, 1, E_,
                                 C, (long long)(H_ * E_), 1,
                                 S_, E_, S_, 1.0f, nullptr);
}

// ---------------------------------------------------------------------------
// Stage 5: out[b,e,s] = sum_k o[b,s,k] * W[e,k] + bias[e]   (single tf32)
// ---------------------------------------------------------------------------
__global__ __launch_bounds__(256, 2) void proj_kernel(
    const float* __restrict__ W, const float* __restrict__ bias,
    float* __restrict__ out)
{
    const int b = blockIdx.z;
    const float* A = g_o + (long long)b * S_ * (H_ * E_);
    float* C = out + (long long)b * E_ * S_;
    mma_gemm<true, true, false>(A, (long long)(H_ * E_), 1,
                                W, (long long)(H_ * E_), 1,
                                C, 1, S_,
                                S_, E_, H_ * E_, 1.0f, bias);
}

// ---------------------------------------------------------------------------
extern "C" void kernel_launch(void* const* d_in, const int* in_sizes, int n_in,
                              void* d_out, int out_size)
{
    (void)in_sizes; (void)n_in; (void)out_size;
    const float* x    = (const float*)d_in[0];
    const float* Qm   = (const float*)d_in[1];
    const float* Km   = (const float*)d_in[2];
    const float* Vm   = (const float*)d_in[3];
    const float* W    = (const float*)d_in[4];
    const float* bias = (const float*)d_in[5];

    float* out = (float*)d_out;
    float* att = out + (long long)B_ * E_ * S_;   // atten region follows out

    const int MT = (S_ + 127) / 128;  // 9

    qkv_kernel    <<<dim3(MT, 1, B_ * H_ * 3), 256>>>(x, Qm, Km, Vm);
    scores_kernel <<<dim3(MT, MT, B_ * H_),    256>>>(att);
    softmax_kernel<<<dim3(B_ * H_ * S_),       256>>>(att);
    av_kernel     <<<dim3(MT, 1, B_ * H_),     256>>>(att);
    proj_kernel   <<<dim3(MT, 1, B_),          256>>>(W, bias, out);
}